// round 13
// baseline (speedup 1.0000x reference)
#include <cuda_runtime.h>
#include <cuda_bf16.h>

// Problem constants
#define SEQ   4096
#define EMB   128
#define HID   128
#define G4    512          // 4*HID gate rows
#define NT    16

// Scratch (device globals; no allocation allowed)
__device__ int   g_tok[SEQ];
__device__ float g_pre[(SEQ + 1) * G4];   // +1 row so prefetch never branches
__device__ float g_hs[SEQ * HID];

typedef unsigned long long ull;

// ---------------------------------------------------------------------------
// fast math helpers
// ---------------------------------------------------------------------------
__device__ __forceinline__ float f_ex2(float x) {
    float y; asm("ex2.approx.f32 %0, %1;" : "=f"(y) : "f"(x)); return y;
}
__device__ __forceinline__ float f_rcp(float x) {
    float y; asm("rcp.approx.f32 %0, %1;" : "=f"(y) : "f"(x)); return y;
}
__device__ __forceinline__ float f_sigmoid(float x) {
    return f_rcp(1.0f + f_ex2(-1.4426950408889634f * x));
}
__device__ __forceinline__ float f_tanh(float x) {
    return 2.0f * f_sigmoid(2.0f * x) - 1.0f;
}

// packed f32x2 ops (sm_100+)
__device__ __forceinline__ ull ffma2(ull a, ull b, ull c) {
    ull d; asm("fma.rn.f32x2 %0, %1, %2, %3;" : "=l"(d) : "l"(a), "l"(b), "l"(c));
    return d;
}
__device__ __forceinline__ ull addf2(ull a, ull b) {
    ull d; asm("add.rn.f32x2 %0, %1, %2;" : "=l"(d) : "l"(a), "l"(b));
    return d;
}
__device__ __forceinline__ ull packf2(float lo, float hi) {
    ull r; asm("mov.b64 %0, {%1, %2};" : "=l"(r) : "f"(lo), "f"(hi)); return r;
}
__device__ __forceinline__ void unpackf2(float& lo, float& hi, ull v) {
    asm("mov.b64 {%0, %1}, %2;" : "=f"(lo), "=f"(hi) : "l"(v));
}
// one LDS.128 delivering two ready-to-use f32x2 operands
__device__ __forceinline__ void lds_v2b64(ull& a, ull& b, unsigned saddr) {
    asm volatile("ld.shared.v2.b64 {%0, %1}, [%2];" : "=l"(a), "=l"(b) : "r"(saddr));
}
// cluster-scope acquire wait on local mbarrier, parity-based
__device__ __forceinline__ void wait_parity_cluster(unsigned mbar, unsigned parity) {
    asm volatile(
        "{\n\t"
        ".reg .pred P;\n\t"
        "WL_%=:\n\t"
        "mbarrier.try_wait.parity.acquire.cluster.shared::cta.b64 P, [%0], %1, 0x989680;\n\t"
        "@P bra.uni WD_%=;\n\t"
        "bra.uni WL_%=;\n\t"
        "WD_%=:\n\t"
        "}"
        :: "r"(mbar), "r"(parity) : "memory");
}

// ---------------------------------------------------------------------------
// Kernel 0: normalize tokens to int32 (int64 delivered as 2x int32, or int32).
// ---------------------------------------------------------------------------
__global__ void tokenize_kernel(const int* __restrict__ xi) {
    __shared__ int is64;
    if (threadIdx.x == 0) {
        int nz = 0;
        #pragma unroll
        for (int i = 0; i < 64; ++i) nz += (xi[2 * i + 1] != 0);
        is64 = (nz == 0);
    }
    __syncthreads();
    int t = blockIdx.x * blockDim.x + threadIdx.x;
    if (t < SEQ) {
        if (is64) g_tok[t] = xi[2 * t];
        else      g_tok[t] = xi[t];
    }
}

// ---------------------------------------------------------------------------
// Kernel 1: pre[t][r] = b_ih[r] + b_hh[r] + sum_k emb[tok[t]][k] * w_ih[r][k]
// ---------------------------------------------------------------------------
__global__ void precompute_kernel(const float* __restrict__ emb,
                                  const float* __restrict__ w_ih,
                                  const float* __restrict__ b_ih,
                                  const float* __restrict__ b_hh,
                                  float* __restrict__ pre) {
    __shared__ float xe[16][128];
    const int t0 = blockIdx.x * 16;

    for (int i = threadIdx.x; i < 16 * 128; i += 256) {
        int ts = i >> 7, k = i & 127;
        long long tok = g_tok[t0 + ts];
        xe[ts][k] = emb[tok * (long long)EMB + k];
    }
    __syncthreads();

    #pragma unroll
    for (int rr = 0; rr < 2; ++rr) {
        const int r = threadIdx.x + rr * 256;
        const float bias = b_ih[r] + b_hh[r];
        float acc[16];
        #pragma unroll
        for (int ts = 0; ts < 16; ++ts) acc[ts] = bias;

        const float4* wrow = reinterpret_cast<const float4*>(w_ih + r * EMB);
        #pragma unroll 8
        for (int k4 = 0; k4 < EMB / 4; ++k4) {
            float4 w = wrow[k4];
            #pragma unroll
            for (int ts = 0; ts < 16; ++ts) {
                float4 h = reinterpret_cast<const float4*>(xe[ts])[k4];
                acc[ts] += w.x * h.x + w.y * h.y + w.z * h.z + w.w * h.w;
            }
        }
        #pragma unroll
        for (int ts = 0; ts < 16; ++ts)
            pre[(t0 + ts) * G4 + r] = acc[ts];
    }
}

// ---------------------------------------------------------------------------
// Kernel 2: recurrence on a 2-CTA cluster. 256 threads/CTA, ONE row/thread,
//   ALL 128 weights in registers (64 f32x2 pairs) — zero weight smem.
//   CTA0: rows 0..255 (i,f). CTA1: rows 256..511 (g,o).
//   Exchange: 256 scalar DSMEM stores into peer recv[parity] + per-thread
//   fence.acq_rel.cluster + __syncthreads + ONE elected remote arrive
//   (count=1). Consumer: one acquire-parity wait. Epilogue redundant in
//   both CTAs on bit-identical inputs; h kept locally in each CTA.
// smem bytes: [0,16) mbar | [16,1040) act_local | [1040,3088) recv[2][256]
//             | [3088,3600) h[128]
// ---------------------------------------------------------------------------
#define SM_MBAR  0
#define SM_ACT   16
#define SM_RECV  1040
#define SM_H     3088
#define LSTM_SMEM_BYTES 3600

__global__ void __launch_bounds__(256, 1) __cluster_dims__(2, 1, 1)
lstm_kernel(const float* __restrict__ w_hh,
            const float* __restrict__ pre,
            float* __restrict__ hs) {
    extern __shared__ char smem[];
    const unsigned sbase = (unsigned)__cvta_generic_to_shared(smem);
    const unsigned mbar  = sbase + SM_MBAR;
    const unsigned act_s = sbase + SM_ACT;
    const unsigned h_s   = sbase + SM_H;
    float* act_f  = reinterpret_cast<float*>(smem + SM_ACT);
    float* recv_f = reinterpret_cast<float*>(smem + SM_RECV);
    float* h_f    = reinterpret_cast<float*>(smem + SM_H);

    const int t    = threadIdx.x;               // 0..255
    const int rank = blockIdx.x;                // grid == one 2-CTA cluster
    const unsigned peer = 1u - (unsigned)rank;
    const int row  = rank * 256 + t;            // global gate row

    // --- ALL 128 weights for my row -> 64 packed f32x2 register pairs ---
    ull wreg[64];
    {
        const float4* wp = reinterpret_cast<const float4*>(w_hh + row * HID);
        #pragma unroll
        for (int i = 0; i < 32; ++i) {
            float4 w = wp[i];
            wreg[2 * i]     = packf2(w.x, w.y);
            wreg[2 * i + 1] = packf2(w.z, w.w);
        }
    }

    // --- remote addresses (computed once) ---
    unsigned rem_recv, rem_mbar;
    asm volatile("mapa.shared::cluster.u32 %0, %1, %2;"
                 : "=r"(rem_recv) : "r"(sbase + SM_RECV), "r"(peer));
    asm volatile("mapa.shared::cluster.u32 %0, %1, %2;"
                 : "=r"(rem_mbar) : "r"(mbar), "r"(peer));

    if (t == 0) {
        asm volatile("mbarrier.init.shared.b64 [%0], %1;" :: "r"(mbar), "r"(1u) : "memory");
    }
    if (t < HID) h_f[t] = 0.0f;
    float c = 0.0f;
    __syncthreads();
    // cluster-wide: both CTAs' mbarrier init + h init visible before use
    asm volatile("barrier.cluster.arrive.aligned;" ::: "memory");
    asm volatile("barrier.cluster.wait.aligned;"   ::: "memory");

    // activation type: CTA1 rows 256..383 (t<128) are the tanh g-gate
    const bool is_tanh = (rank == 1) && (t < 128);
    float pre_cur = pre[row];

    for (int s = 0; s < SEQ; ++s) {
        const unsigned p = (unsigned)(s & 1);
        float pre_next = pre[(s + 1) * G4 + row];   // prefetch (row SEQ exists)

        // --- dot: 128 weights all in registers, h broadcast from local smem ---
        ull a0 = packf2(pre_cur, 0.0f), a1 = 0, a2 = 0, a3 = 0;
        #pragma unroll
        for (int i = 0; i < 16; ++i) {
            ull hp0, hp1, hp2, hp3;
            lds_v2b64(hp0, hp1, h_s + 32u * i);
            lds_v2b64(hp2, hp3, h_s + 32u * i + 16u);
            a0 = ffma2(wreg[4 * i],     hp0, a0);
            a1 = ffma2(wreg[4 * i + 1], hp1, a1);
            a2 = ffma2(wreg[4 * i + 2], hp2, a2);
            a3 = ffma2(wreg[4 * i + 3], hp3, a3);
        }
        ull sT = addf2(addf2(a0, a1), addf2(a2, a3));
        float zlo, zhi;
        unpackf2(zlo, zhi, sT);
        float z = zlo + zhi;
        pre_cur = pre_next;

        float a = is_tanh ? f_tanh(z) : f_sigmoid(z);

        // --- exchange: local copy + direct remote scalar store + fence ---
        asm volatile("st.shared.f32 [%0], %1;" :: "r"(act_s + 4u * t), "f"(a) : "memory");
        asm volatile("st.shared::cluster.f32 [%0], %1;"
                     :: "r"(rem_recv + p * 1024u + 4u * t), "f"(a) : "memory");
        asm volatile("fence.acq_rel.cluster;" ::: "memory");
        __syncthreads();                            // all stores + fences done

        if (t == 0) {
            asm volatile("mbarrier.arrive.release.cluster.shared::cluster.b64 _, [%0];"
                         :: "r"(rem_mbar) : "memory");
        }

        // wait for the peer's 256 activations (its single arrive)
        wait_parity_cluster(mbar, p);

        if (t < HID) {
            float l0 = act_f[t];                    // own-CTA gate (i or g)
            float l1 = act_f[t + 128];              // own-CTA gate (f or o)
            float r0 = recv_f[p * 256 + t];         // peer gate
            float r1 = recv_f[p * 256 + t + 128];
            float ig = rank ? r0 : l0;
            float fg = rank ? r1 : l1;
            float gg = rank ? l0 : r0;
            float og = rank ? l1 : r1;
            c = fg * c + ig * gg;
            float hv = og * f_tanh(c);
            h_f[t] = hv;
            if (rank == 0) hs[s * HID + t] = hv;
        }
        __syncthreads();                            // h ready for next dot
    }
    // keep CTAs co-resident until both finish (peer may still access DSMEM)
    asm volatile("barrier.cluster.arrive.aligned;" ::: "memory");
    asm volatile("barrier.cluster.wait.aligned;"   ::: "memory");
}

// ---------------------------------------------------------------------------
// Kernel 3: out[t][n] = b_fc[n] + sum_k hs[t][k] * w_fc[n][k]
// ---------------------------------------------------------------------------
__global__ void fc_kernel(const float* __restrict__ hs,
                          const float* __restrict__ w_fc,
                          const float* __restrict__ b_fc,
                          float* __restrict__ out) {
    __shared__ float sh[16][132];
    __shared__ float sw[16][132];
    const int t0 = blockIdx.x * 16;

    for (int i = threadIdx.x; i < 16 * 128; i += 256) {
        int rr = i >> 7, k = i & 127;
        sh[rr][k] = hs[(t0 + rr) * HID + k];
        sw[rr][k] = w_fc[rr * HID + k];
    }
    __syncthreads();

    const int ts = threadIdx.x >> 4;
    const int n  = threadIdx.x & 15;
    float acc = b_fc[n];
    #pragma unroll 8
    for (int k = 0; k < 128; ++k)
        acc += sh[ts][k] * sw[n][k];
    out[(t0 + ts) * NT + n] = acc;
}

// ---------------------------------------------------------------------------
extern "C" void kernel_launch(void* const* d_in, const int* in_sizes, int n_in,
                              void* d_out, int out_size) {
    const int*   x    = (const int*)d_in[0];
    const float* emb  = (const float*)d_in[1];
    const float* w_ih = (const float*)d_in[2];
    const float* w_hh = (const float*)d_in[3];
    const float* b_ih = (const float*)d_in[4];
    const float* b_hh = (const float*)d_in[5];
    const float* w_fc = (const float*)d_in[6];
    const float* b_fc = (const float*)d_in[7];
    float* out = (float*)d_out;

    float* pre; cudaGetSymbolAddress((void**)&pre, g_pre);
    float* hs;  cudaGetSymbolAddress((void**)&hs,  g_hs);

    cudaFuncSetAttribute(lstm_kernel,
                         cudaFuncAttributeMaxDynamicSharedMemorySize, LSTM_SMEM_BYTES);

    tokenize_kernel<<<SEQ / 256, 256>>>(x);
    precompute_kernel<<<SEQ / 16, 256>>>(emb, w_ih, b_ih, b_hh, pre);
    lstm_kernel<<<2, 256, LSTM_SMEM_BYTES>>>(w_hh, pre, hs);
    fc_kernel<<<SEQ / 16, 256>>>(hs, w_fc, b_fc, out);
}

// round 14
// speedup vs baseline: 1.4062x; 1.4062x over previous
#include <cuda_runtime.h>
#include <cuda_bf16.h>

// Problem constants
#define SEQ   4096
#define EMB   128
#define HID   128
#define G4    512          // 4*HID gate rows
#define NT    16

// Scratch (device globals; no allocation allowed)
__device__ int   g_tok[SEQ];
__device__ float g_pre[(SEQ + 1) * G4];   // +1 row so prefetch never branches
__device__ float g_hs[SEQ * HID];

typedef unsigned long long ull;

// ---------------------------------------------------------------------------
// fast math helpers
// ---------------------------------------------------------------------------
__device__ __forceinline__ float f_ex2(float x) {
    float y; asm("ex2.approx.f32 %0, %1;" : "=f"(y) : "f"(x)); return y;
}
__device__ __forceinline__ float f_rcp(float x) {
    float y; asm("rcp.approx.f32 %0, %1;" : "=f"(y) : "f"(x)); return y;
}
__device__ __forceinline__ float f_sigmoid(float x) {
    return f_rcp(1.0f + f_ex2(-1.4426950408889634f * x));
}
__device__ __forceinline__ float f_tanh(float x) {
    return 2.0f * f_sigmoid(2.0f * x) - 1.0f;
}

// packed f32x2 FMA (sm_100+)
__device__ __forceinline__ ull ffma2(ull a, ull b, ull c) {
    ull d; asm("fma.rn.f32x2 %0, %1, %2, %3;" : "=l"(d) : "l"(a), "l"(b), "l"(c));
    return d;
}
__device__ __forceinline__ ull packf2(float lo, float hi) {
    ull r; asm("mov.b64 %0, {%1, %2};" : "=l"(r) : "f"(lo), "f"(hi)); return r;
}
__device__ __forceinline__ void unpackf2(float& lo, float& hi, ull v) {
    asm("mov.b64 {%0, %1}, %2;" : "=f"(lo), "=f"(hi) : "l"(v));
}
// one LDS.128 delivering two ready-to-use f32x2 operands
__device__ __forceinline__ void lds_v2b64(ull& a, ull& b, unsigned saddr) {
    asm volatile("ld.shared.v2.b64 {%0, %1}, [%2];" : "=l"(a), "=l"(b) : "r"(saddr));
}

// ---------------------------------------------------------------------------
// Kernel 0: normalize tokens to int32 (int64 delivered as 2x int32, or int32).
// ---------------------------------------------------------------------------
__global__ void tokenize_kernel(const int* __restrict__ xi) {
    __shared__ int is64;
    if (threadIdx.x == 0) {
        int nz = 0;
        #pragma unroll
        for (int i = 0; i < 64; ++i) nz += (xi[2 * i + 1] != 0);
        is64 = (nz == 0);
    }
    __syncthreads();
    int t = blockIdx.x * blockDim.x + threadIdx.x;
    if (t < SEQ) {
        if (is64) g_tok[t] = xi[2 * t];
        else      g_tok[t] = xi[t];
    }
}

// ---------------------------------------------------------------------------
// Kernel 1: pre[t][r] = b_ih[r] + b_hh[r] + sum_k emb[tok[t]][k] * w_ih[r][k]
// ---------------------------------------------------------------------------
__global__ void precompute_kernel(const float* __restrict__ emb,
                                  const float* __restrict__ w_ih,
                                  const float* __restrict__ b_ih,
                                  const float* __restrict__ b_hh,
                                  float* __restrict__ pre) {
    __shared__ float xe[16][128];
    const int t0 = blockIdx.x * 16;

    for (int i = threadIdx.x; i < 16 * 128; i += 256) {
        int ts = i >> 7, k = i & 127;
        long long tok = g_tok[t0 + ts];
        xe[ts][k] = emb[tok * (long long)EMB + k];
    }
    __syncthreads();

    #pragma unroll
    for (int rr = 0; rr < 2; ++rr) {
        const int r = threadIdx.x + rr * 256;
        const float bias = b_ih[r] + b_hh[r];
        float acc[16];
        #pragma unroll
        for (int ts = 0; ts < 16; ++ts) acc[ts] = bias;

        const float4* wrow = reinterpret_cast<const float4*>(w_ih + r * EMB);
        #pragma unroll 8
        for (int k4 = 0; k4 < EMB / 4; ++k4) {
            float4 w = wrow[k4];
            #pragma unroll
            for (int ts = 0; ts < 16; ++ts) {
                float4 h = reinterpret_cast<const float4*>(xe[ts])[k4];
                acc[ts] += w.x * h.x + w.y * h.y + w.z * h.z + w.w * h.w;
            }
        }
        #pragma unroll
        for (int ts = 0; ts < 16; ++ts)
            pre[(t0 + ts) * G4 + r] = acc[ts];
    }
}

// ---------------------------------------------------------------------------
// Kernel 2: recurrence. 1 block x 256 threads; thread r owns TWO gate rows:
//   rA = r, rB = r + 256. For r<128: (i, g); for r>=128: (f, o).
//   ONE shared h-load stream feeds both dots.
//   Per row: w[0:108] in 54 packed f32x2 register pairs (216 regs total),
//            w[108:128] in smem (stride-20 rows, phase-conflict-free).
//   Epilogue: only f,o cross threads — packed float2 through zfo[].
// ---------------------------------------------------------------------------
#define NREG   108
#define NSH    (HID - NREG)       // 20
#define WS_STRIDE 20              // 20-float stride; 20l mod 32 distinct/phase

__global__ void __launch_bounds__(256, 1)
lstm_kernel(const float* __restrict__ w_hh,
            const float* __restrict__ pre,
            float* __restrict__ hs) {
    extern __shared__ float smem[];
    float*  ws  = smem;                          // 512 * 20 floats (40960 B)
    float*  h_s = ws + G4 * WS_STRIDE;           // 128 floats (16B aligned)
    float2* zfo = reinterpret_cast<float2*>(h_s + HID);  // 128 float2

    const int r  = threadIdx.x;                  // 0..255
    const int rA = r;                            // i (r<128) / f gate rows
    const int rB = r + 256;                      // g (r<128) / o gate rows

    // --- pack register weights for both rows: [0:108] -> 54 pairs each ---
    ull wa[NREG / 2], wb[NREG / 2];
    {
        const float4* wrA = reinterpret_cast<const float4*>(w_hh + rA * HID);
        const float4* wrB = reinterpret_cast<const float4*>(w_hh + rB * HID);
        #pragma unroll
        for (int i = 0; i < NREG / 4; ++i) {
            float4 w = wrA[i];
            wa[2 * i]     = packf2(w.x, w.y);
            wa[2 * i + 1] = packf2(w.z, w.w);
            float4 v = wrB[i];
            wb[2 * i]     = packf2(v.x, v.y);
            wb[2 * i + 1] = packf2(v.z, v.w);
        }
    }
    // --- smem tails for all 512 rows: ws[row][k] = w_hh[row][108+k] ---
    for (int idx = r; idx < G4 * NSH; idx += 256) {
        int row = idx / NSH, k = idx - row * NSH;
        ws[row * WS_STRIDE + k] = w_hh[row * HID + NREG + k];
    }
    if (r < HID) h_s[r] = 0.0f;
    float c = 0.0f;

    const unsigned h_saddr = (unsigned)__cvta_generic_to_shared(h_s);
    const unsigned wsA     = (unsigned)__cvta_generic_to_shared(ws + rA * WS_STRIDE);
    const unsigned wsB     = (unsigned)__cvta_generic_to_shared(ws + rB * WS_STRIDE);
    const bool lo_half = (r < 128);              // (i,g) pair vs (f,o) pair

    float preA = pre[rA];
    float preB = pre[rB];
    __syncthreads();

    for (int s = 0; s < SEQ; ++s) {
        ull a0 = packf2(preA, 0.0f), a1 = 0, a2 = 0, a3 = 0;
        ull b0 = packf2(preB, 0.0f), b1 = 0, b2 = 0, b3 = 0;
        preA = pre[(s + 1) * G4 + rA];           // prefetch (row SEQ exists)
        preB = pre[(s + 1) * G4 + rB];

        // --- smem weight tail FIRST (h chunks 27..31), latency hides below ---
        #pragma unroll
        for (int i = 0; i < NSH / 4; ++i) {
            ull hp0, hp1, wa0, wa1, wb0, wb1;
            lds_v2b64(hp0, hp1, h_saddr + 16u * (NREG / 4 + i));
            lds_v2b64(wa0, wa1, wsA + 16u * i);
            lds_v2b64(wb0, wb1, wsB + 16u * i);
            a0 = ffma2(wa0, hp0, a0);  a1 = ffma2(wa1, hp1, a1);
            b0 = ffma2(wb0, hp0, b0);  b1 = ffma2(wb1, hp1, b1);
        }
        // --- register-resident 108: one h load feeds BOTH rows ---
        #pragma unroll
        for (int i = 0; i < NREG / 4; ++i) {
            ull hp0, hp1;
            lds_v2b64(hp0, hp1, h_saddr + 16u * i);
            a2 = ffma2(wa[2 * i],     hp0, a2);
            a3 = ffma2(wa[2 * i + 1], hp1, a3);
            b2 = ffma2(wb[2 * i],     hp0, b2);
            b3 = ffma2(wb[2 * i + 1], hp1, b3);
        }

        float x0, x1, x2, x3, x4, x5, x6, x7;
        unpackf2(x0, x1, a0); unpackf2(x2, x3, a1);
        unpackf2(x4, x5, a2); unpackf2(x6, x7, a3);
        float zA = ((x0 + x1) + (x2 + x3)) + ((x4 + x5) + (x6 + x7));
        unpackf2(x0, x1, b0); unpackf2(x2, x3, b1);
        unpackf2(x4, x5, b2); unpackf2(x6, x7, b3);
        float zB = ((x0 + x1) + (x2 + x3)) + ((x4 + x5) + (x6 + x7));

        float aA = f_sigmoid(zA);                          // i or f
        float aB = lo_half ? f_tanh(zB) : f_sigmoid(zB);   // g or o

        if (!lo_half) zfo[r - 128] = make_float2(aA, aB);  // {f, o}
        __syncthreads();

        if (lo_half) {
            float2 fo = zfo[r];                 // one LDS.64
            c = fo.x * c + aA * aB;             // f*c + i*g (both local!)
            float hv = fo.y * f_tanh(c);        // o * tanh(c)
            h_s[r] = hv;
            hs[s * HID + r] = hv;
        }
        __syncthreads();
    }
}

// ---------------------------------------------------------------------------
// Kernel 3: out[t][n] = b_fc[n] + sum_k hs[t][k] * w_fc[n][k]
// ---------------------------------------------------------------------------
__global__ void fc_kernel(const float* __restrict__ hs,
                          const float* __restrict__ w_fc,
                          const float* __restrict__ b_fc,
                          float* __restrict__ out) {
    __shared__ float sh[16][132];
    __shared__ float sw[16][132];
    const int t0 = blockIdx.x * 16;

    for (int i = threadIdx.x; i < 16 * 128; i += 256) {
        int rr = i >> 7, k = i & 127;
        sh[rr][k] = hs[(t0 + rr) * HID + k];
        sw[rr][k] = w_fc[rr * HID + k];
    }
    __syncthreads();

    const int ts = threadIdx.x >> 4;
    const int n  = threadIdx.x & 15;
    float acc = b_fc[n];
    #pragma unroll 8
    for (int k = 0; k < 128; ++k)
        acc += sh[ts][k] * sw[n][k];
    out[(t0 + ts) * NT + n] = acc;
}

// ---------------------------------------------------------------------------
extern "C" void kernel_launch(void* const* d_in, const int* in_sizes, int n_in,
                              void* d_out, int out_size) {
    const int*   x    = (const int*)d_in[0];
    const float* emb  = (const float*)d_in[1];
    const float* w_ih = (const float*)d_in[2];
    const float* w_hh = (const float*)d_in[3];
    const float* b_ih = (const float*)d_in[4];
    const float* b_hh = (const float*)d_in[5];
    const float* w_fc = (const float*)d_in[6];
    const float* b_fc = (const float*)d_in[7];
    float* out = (float*)d_out;

    float* pre; cudaGetSymbolAddress((void**)&pre, g_pre);
    float* hs;  cudaGetSymbolAddress((void**)&hs,  g_hs);

    const int lstm_smem = (G4 * WS_STRIDE + HID + 2 * HID) * (int)sizeof(float);
    cudaFuncSetAttribute(lstm_kernel,
                         cudaFuncAttributeMaxDynamicSharedMemorySize, lstm_smem);

    tokenize_kernel<<<SEQ / 256, 256>>>(x);
    precompute_kernel<<<SEQ / 16, 256>>>(emb, w_ih, b_ih, b_hh, pre);
    lstm_kernel<<<1, 256, lstm_smem>>>(w_hh, pre, hs);
    fc_kernel<<<SEQ / 16, 256>>>(hs, w_fc, b_fc, out);
}

// round 15
// speedup vs baseline: 1.4220x; 1.0112x over previous
#include <cuda_runtime.h>
#include <cuda_bf16.h>

// Problem constants
#define SEQ   4096
#define EMB   128
#define HID   128
#define G4    512          // 4*HID gate rows
#define NT    16

// Scratch (device globals; no allocation allowed)
__device__ int   g_tok[SEQ];
__device__ float g_pre[(SEQ + 1) * G4];   // +1 row so prefetch never branches
__device__ float g_hs[SEQ * HID];

typedef unsigned long long ull;

// ---------------------------------------------------------------------------
// fast math helpers
// ---------------------------------------------------------------------------
__device__ __forceinline__ float f_ex2(float x) {
    float y; asm("ex2.approx.f32 %0, %1;" : "=f"(y) : "f"(x)); return y;
}
__device__ __forceinline__ float f_rcp(float x) {
    float y; asm("rcp.approx.f32 %0, %1;" : "=f"(y) : "f"(x)); return y;
}
__device__ __forceinline__ float f_sigmoid(float x) {
    return f_rcp(1.0f + f_ex2(-1.4426950408889634f * x));
}
__device__ __forceinline__ float f_tanh(float x) {
    return 2.0f * f_sigmoid(2.0f * x) - 1.0f;
}

// packed f32x2 ops (sm_100+)
__device__ __forceinline__ ull ffma2(ull a, ull b, ull c) {
    ull d; asm("fma.rn.f32x2 %0, %1, %2, %3;" : "=l"(d) : "l"(a), "l"(b), "l"(c));
    return d;
}
__device__ __forceinline__ ull addf2(ull a, ull b) {
    ull d; asm("add.rn.f32x2 %0, %1, %2;" : "=l"(d) : "l"(a), "l"(b));
    return d;
}
__device__ __forceinline__ ull packf2(float lo, float hi) {
    ull r; asm("mov.b64 %0, {%1, %2};" : "=l"(r) : "f"(lo), "f"(hi)); return r;
}
__device__ __forceinline__ void unpackf2(float& lo, float& hi, ull v) {
    asm("mov.b64 {%0, %1}, %2;" : "=f"(lo), "=f"(hi) : "l"(v));
}
// one LDS.128 delivering two ready-to-use f32x2 operands
__device__ __forceinline__ void lds_v2b64(ull& a, ull& b, unsigned saddr) {
    asm volatile("ld.shared.v2.b64 {%0, %1}, [%2];" : "=l"(a), "=l"(b) : "r"(saddr));
}

// ---------------------------------------------------------------------------
// Kernel 0: normalize tokens to int32 (int64 delivered as 2x int32, or int32).
// ---------------------------------------------------------------------------
__global__ void tokenize_kernel(const int* __restrict__ xi) {
    __shared__ int is64;
    if (threadIdx.x == 0) {
        int nz = 0;
        #pragma unroll
        for (int i = 0; i < 64; ++i) nz += (xi[2 * i + 1] != 0);
        is64 = (nz == 0);
    }
    __syncthreads();
    int t = blockIdx.x * blockDim.x + threadIdx.x;
    if (t < SEQ) {
        if (is64) g_tok[t] = xi[2 * t];
        else      g_tok[t] = xi[t];
    }
}

// ---------------------------------------------------------------------------
// Kernel 1: pre[t][r] = b_ih[r] + b_hh[r] + sum_k emb[tok[t]][k] * w_ih[r][k]
// ---------------------------------------------------------------------------
__global__ void precompute_kernel(const float* __restrict__ emb,
                                  const float* __restrict__ w_ih,
                                  const float* __restrict__ b_ih,
                                  const float* __restrict__ b_hh,
                                  float* __restrict__ pre) {
    __shared__ float xe[16][128];
    const int t0 = blockIdx.x * 16;

    for (int i = threadIdx.x; i < 16 * 128; i += 256) {
        int ts = i >> 7, k = i & 127;
        long long tok = g_tok[t0 + ts];
        xe[ts][k] = emb[tok * (long long)EMB + k];
    }
    __syncthreads();

    #pragma unroll
    for (int rr = 0; rr < 2; ++rr) {
        const int r = threadIdx.x + rr * 256;
        const float bias = b_ih[r] + b_hh[r];
        float acc[16];
        #pragma unroll
        for (int ts = 0; ts < 16; ++ts) acc[ts] = bias;

        const float4* wrow = reinterpret_cast<const float4*>(w_ih + r * EMB);
        #pragma unroll 8
        for (int k4 = 0; k4 < EMB / 4; ++k4) {
            float4 w = wrow[k4];
            #pragma unroll
            for (int ts = 0; ts < 16; ++ts) {
                float4 h = reinterpret_cast<const float4*>(xe[ts])[k4];
                acc[ts] += w.x * h.x + w.y * h.y + w.z * h.z + w.w * h.w;
            }
        }
        #pragma unroll
        for (int ts = 0; ts < 16; ++ts)
            pre[(t0 + ts) * G4 + r] = acc[ts];
    }
}

// ---------------------------------------------------------------------------
// Kernel 2: recurrence. 1 block x 256 threads; thread r owns TWO gate rows:
//   rA = r, rB = r + 256. For r<128: (i, g); for r>=128: (f, o).
//   ONE shared h-load stream feeds both dots.
//   Per row: w[0:112] in 56 packed f32x2 register pairs (224 regs total),
//            w[112:128] in smem (stride-20 rows, phase-conflict-free).
//   Only 4 accumulators (8 regs) to stay under the 255-reg cap.
//   Epilogue: only f,o cross threads — packed float2 through zfo[].
// ---------------------------------------------------------------------------
#define NREG   112
#define NSH    (HID - NREG)       // 16
#define WS_STRIDE 20              // 16 + 4 pad; 20l mod 32 distinct per phase

__global__ void __launch_bounds__(256, 1)
lstm_kernel(const float* __restrict__ w_hh,
            const float* __restrict__ pre,
            float* __restrict__ hs) {
    extern __shared__ float smem[];
    float*  ws  = smem;                          // 512 * 20 floats (40960 B)
    float*  h_s = ws + G4 * WS_STRIDE;           // 128 floats (16B aligned)
    float2* zfo = reinterpret_cast<float2*>(h_s + HID);  // 128 float2

    const int r  = threadIdx.x;                  // 0..255
    const int rA = r;                            // i (r<128) / f gate rows
    const int rB = r + 256;                      // g (r<128) / o gate rows

    // --- pack register weights for both rows: [0:112] -> 56 pairs each ---
    ull wa[NREG / 2], wb[NREG / 2];
    {
        const float4* wrA = reinterpret_cast<const float4*>(w_hh + rA * HID);
        const float4* wrB = reinterpret_cast<const float4*>(w_hh + rB * HID);
        #pragma unroll
        for (int i = 0; i < NREG / 4; ++i) {
            float4 w = wrA[i];
            wa[2 * i]     = packf2(w.x, w.y);
            wa[2 * i + 1] = packf2(w.z, w.w);
            float4 v = wrB[i];
            wb[2 * i]     = packf2(v.x, v.y);
            wb[2 * i + 1] = packf2(v.z, v.w);
        }
    }
    // --- smem tails for all 512 rows: ws[row][k] = w_hh[row][112+k] ---
    for (int idx = r; idx < G4 * NSH; idx += 256) {
        int row = idx >> 4, k = idx & (NSH - 1);
        ws[row * WS_STRIDE + k] = w_hh[row * HID + NREG + k];
    }
    if (r < HID) h_s[r] = 0.0f;
    float c = 0.0f;

    const unsigned h_saddr = (unsigned)__cvta_generic_to_shared(h_s);
    const unsigned wsA     = (unsigned)__cvta_generic_to_shared(ws + rA * WS_STRIDE);
    const unsigned wsB     = (unsigned)__cvta_generic_to_shared(ws + rB * WS_STRIDE);
    const bool lo_half = (r < 128);              // (i,g) pair vs (f,o) pair

    float preA = pre[rA];
    float preB = pre[rB];
    __syncthreads();

    for (int s = 0; s < SEQ; ++s) {
        ull a0 = packf2(preA, 0.0f), a1 = 0;
        ull b0 = packf2(preB, 0.0f), b1 = 0;
        preA = pre[(s + 1) * G4 + rA];           // prefetch (row SEQ exists)
        preB = pre[(s + 1) * G4 + rB];

        // --- smem weight tail FIRST (h chunks 28..31), latency hides below ---
        #pragma unroll
        for (int i = 0; i < NSH / 4; ++i) {
            ull hp0, hp1, wa0, wa1, wb0, wb1;
            lds_v2b64(hp0, hp1, h_saddr + 16u * (NREG / 4 + i));
            lds_v2b64(wa0, wa1, wsA + 16u * i);
            lds_v2b64(wb0, wb1, wsB + 16u * i);
            a0 = ffma2(wa0, hp0, a0);  a1 = ffma2(wa1, hp1, a1);
            b0 = ffma2(wb0, hp0, b0);  b1 = ffma2(wb1, hp1, b1);
        }
        // --- register-resident 112: one h load feeds BOTH rows ---
        #pragma unroll
        for (int i = 0; i < NREG / 4; ++i) {
            ull hp0, hp1;
            lds_v2b64(hp0, hp1, h_saddr + 16u * i);
            a0 = ffma2(wa[2 * i],     hp0, a0);
            a1 = ffma2(wa[2 * i + 1], hp1, a1);
            b0 = ffma2(wb[2 * i],     hp0, b0);
            b1 = ffma2(wb[2 * i + 1], hp1, b1);
        }

        // packed reduction trees
        ull sa = addf2(a0, a1);
        ull sb = addf2(b0, b1);
        float xa0, xa1, xb0, xb1;
        unpackf2(xa0, xa1, sa);
        unpackf2(xb0, xb1, sb);
        float zA = xa0 + xa1;
        float zB = xb0 + xb1;

        float aA = f_sigmoid(zA);                          // i or f
        float aB = lo_half ? f_tanh(zB) : f_sigmoid(zB);   // g or o

        if (!lo_half) zfo[r - 128] = make_float2(aA, aB);  // {f, o}
        __syncthreads();

        if (lo_half) {
            float2 fo = zfo[r];                 // one LDS.64
            c = fo.x * c + aA * aB;             // f*c + i*g (both local!)
            float hv = fo.y * f_tanh(c);        // o * tanh(c)
            h_s[r] = hv;
            hs[s * HID + r] = hv;
        }
        __syncthreads();
    }
}

// ---------------------------------------------------------------------------
// Kernel 3: out[t][n] = b_fc[n] + sum_k hs[t][k] * w_fc[n][k]
// ---------------------------------------------------------------------------
__global__ void fc_kernel(const float* __restrict__ hs,
                          const float* __restrict__ w_fc,
                          const float* __restrict__ b_fc,
                          float* __restrict__ out) {
    __shared__ float sh[16][132];
    __shared__ float sw[16][132];
    const int t0 = blockIdx.x * 16;

    for (int i = threadIdx.x; i < 16 * 128; i += 256) {
        int rr = i >> 7, k = i & 127;
        sh[rr][k] = hs[(t0 + rr) * HID + k];
        sw[rr][k] = w_fc[rr * HID + k];
    }
    __syncthreads();

    const int ts = threadIdx.x >> 4;
    const int n  = threadIdx.x & 15;
    float acc = b_fc[n];
    #pragma unroll 8
    for (int k = 0; k < 128; ++k)
        acc += sh[ts][k] * sw[n][k];
    out[(t0 + ts) * NT + n] = acc;
}

// ---------------------------------------------------------------------------
extern "C" void kernel_launch(void* const* d_in, const int* in_sizes, int n_in,
                              void* d_out, int out_size) {
    const int*   x    = (const int*)d_in[0];
    const float* emb  = (const float*)d_in[1];
    const float* w_ih = (const float*)d_in[2];
    const float* w_hh = (const float*)d_in[3];
    const float* b_ih = (const float*)d_in[4];
    const float* b_hh = (const float*)d_in[5];
    const float* w_fc = (const float*)d_in[6];
    const float* b_fc = (const float*)d_in[7];
    float* out = (float*)d_out;

    float* pre; cudaGetSymbolAddress((void**)&pre, g_pre);
    float* hs;  cudaGetSymbolAddress((void**)&hs,  g_hs);

    const int lstm_smem = (G4 * WS_STRIDE + HID + 2 * HID) * (int)sizeof(float);
    cudaFuncSetAttribute(lstm_kernel,
                         cudaFuncAttributeMaxDynamicSharedMemorySize, lstm_smem);

    tokenize_kernel<<<SEQ / 256, 256>>>(x);
    precompute_kernel<<<SEQ / 16, 256>>>(emb, w_ih, b_ih, b_hh, pre);
    lstm_kernel<<<1, 256, lstm_smem>>>(w_hh, pre, hs);
    fc_kernel<<<SEQ / 16, 256>>>(hs, w_fc, b_fc, out);
}